// round 2
// baseline (speedup 1.0000x reference)
#include <cuda_runtime.h>

// Problem constants (fixed by the dataset)
#define MAXN 50000
#define MAXE 800000

// Persistent device scratch (allocation-free rule: __device__ globals)
static __device__ __align__(16) float g_sup[MAXN * 32];     // s_up   [n][c]
static __device__ __align__(16) float g_vup[MAXN * 96];     // v_up   [n][x][c]
static __device__ __align__(16) float g_skip_s[MAXN * 64];  // skip_s [n][d]
static __device__ __align__(16) float g_skip_v[MAXN * 96];  // skip_v [n][x][c]
static __device__ __align__(16) float g_agg[MAXN * 256];    // [n][slot][c]

// CSR-by-receiver scratch
static __device__ int g_cnt[MAXN];
static __device__ int g_off[MAXN + 1];
static __device__ int g_cur[MAXN];
static __device__ int g_bsum[64];
static __device__ int g_sorted[MAXE];

__device__ __forceinline__ float silu_f(float x) {
    return x / (1.0f + __expf(-x));
}

// ---------------------------------------------------------------------------
// Kernel A: per-node up-projection + species skip. Warp per node; lane = chan.
// Also zeroes the receiver histogram.
// ---------------------------------------------------------------------------
__global__ void node_up_kernel(const float* __restrict__ nf,
                               const int*   __restrict__ species,
                               const float* __restrict__ Wus,   // (32,32)
                               const float* __restrict__ Wuv,   // (32,32)
                               const float* __restrict__ Wss,   // (5,32,64)
                               const float* __restrict__ Wsv,   // (5,32,32)
                               int N)
{
    int warp = (blockIdx.x * blockDim.x + threadIdx.x) >> 5;
    int lane = threadIdx.x & 31;
    if (warp >= N) return;
    int n = warp;

    if (lane == 0) g_cnt[n] = 0;

    const float* nfp = nf + (size_t)n * 128;
    float s  = nfp[lane];
    float v0 = nfp[32 + lane * 3 + 0];
    float v1 = nfp[32 + lane * 3 + 1];
    float v2 = nfp[32 + lane * 3 + 2];
    int sp = species[n];
    const float* wss = Wss + sp * 2048;
    const float* wsv = Wsv + sp * 1024;

    float sup = 0.f, vu0 = 0.f, vu1 = 0.f, vu2 = 0.f;
    float ss0 = 0.f, ss1 = 0.f, sv0 = 0.f, sv1 = 0.f, sv2 = 0.f;

    #pragma unroll
    for (int c = 0; c < 32; ++c) {
        float sb = __shfl_sync(0xffffffffu, s,  c);
        float b0 = __shfl_sync(0xffffffffu, v0, c);
        float b1 = __shfl_sync(0xffffffffu, v1, c);
        float b2 = __shfl_sync(0xffffffffu, v2, c);
        sup = fmaf(sb, __ldg(Wus + c * 32 + lane), sup);
        float wu = __ldg(Wuv + c * 32 + lane);
        vu0 = fmaf(b0, wu, vu0);
        vu1 = fmaf(b1, wu, vu1);
        vu2 = fmaf(b2, wu, vu2);
        ss0 = fmaf(sb, __ldg(wss + c * 64 + lane), ss0);
        ss1 = fmaf(sb, __ldg(wss + c * 64 + 32 + lane), ss1);
        float wv = __ldg(wsv + c * 32 + lane);
        sv0 = fmaf(b0, wv, sv0);
        sv1 = fmaf(b1, wv, sv1);
        sv2 = fmaf(b2, wv, sv2);
    }

    const float isc = 0.17677669529663687f; // 1/sqrt(32)
    g_sup[n * 32 + lane]             = sup * isc;
    g_vup[n * 96 + 0 * 32 + lane]    = vu0 * isc;
    g_vup[n * 96 + 1 * 32 + lane]    = vu1 * isc;
    g_vup[n * 96 + 2 * 32 + lane]    = vu2 * isc;
    g_skip_s[n * 64 + lane]          = ss0 * isc;
    g_skip_s[n * 64 + 32 + lane]     = ss1 * isc;
    g_skip_v[n * 96 + 0 * 32 + lane] = sv0 * isc;
    g_skip_v[n * 96 + 1 * 32 + lane] = sv1 * isc;
    g_skip_v[n * 96 + 2 * 32 + lane] = sv2 * isc;
}

// ---------------------------------------------------------------------------
// Counting sort by receiver: histogram -> scan (3 phases) -> reorder
// ---------------------------------------------------------------------------
__global__ void hist_kernel(const int* __restrict__ rcv, int E)
{
    int e = blockIdx.x * blockDim.x + threadIdx.x;
    if (e < E) atomicAdd(&g_cnt[__ldg(rcv + e)], 1);
}

__global__ void scan1_kernel(int N)
{
    __shared__ int wsum[32];
    int t = threadIdx.x, b = blockIdx.x;
    int idx = b * 1024 + t;
    int val = (idx < N) ? g_cnt[idx] : 0;
    int lane = t & 31, wid = t >> 5;
    int x = val;
    #pragma unroll
    for (int o = 1; o < 32; o <<= 1) {
        int y = __shfl_up_sync(0xffffffffu, x, o);
        if (lane >= o) x += y;
    }
    if (lane == 31) wsum[wid] = x;
    __syncthreads();
    if (wid == 0) {
        int w = wsum[lane];
        #pragma unroll
        for (int o = 1; o < 32; o <<= 1) {
            int y = __shfl_up_sync(0xffffffffu, w, o);
            if (lane >= o) w += y;
        }
        wsum[lane] = w;
    }
    __syncthreads();
    int basev = wid ? wsum[wid - 1] : 0;
    int incl = x + basev;
    if (idx < N) g_off[idx] = incl - val;   // block-local exclusive
    if (t == 1023) g_bsum[b] = incl;        // block total
}

__global__ void scan2_kernel(int nb, int N)
{
    if (threadIdx.x == 0 && blockIdx.x == 0) {
        int run = 0;
        for (int b = 0; b < nb; ++b) { int v = g_bsum[b]; g_bsum[b] = run; run += v; }
        g_off[N] = run;
    }
}

__global__ void scan3_kernel(int N)
{
    int idx = blockIdx.x * 1024 + threadIdx.x;
    if (idx < N) {
        int o = g_off[idx] + g_bsum[blockIdx.x];
        g_off[idx] = o;
        g_cur[idx] = o;
    }
}

__global__ void reorder_kernel(const int* __restrict__ rcv, int E)
{
    int e = blockIdx.x * blockDim.x + threadIdx.x;
    if (e < E) {
        int pos = atomicAdd(&g_cur[__ldg(rcv + e)], 1);
        g_sorted[pos] = e;
    }
}

// ---------------------------------------------------------------------------
// Kernel B: node-centric message aggregation. Warp per receiver node.
// Accumulates in registers (no atomics), writes g_agg with plain stores.
// Lane layout (identical to round-1 verified edge kernel):
//   producer lane P computes w[path=P>>3][4*(P&7)..+3]
//   consumer lane L owns quad qA = slot(L>>4), chans 4*(L&15);  qB = slot+2
// ---------------------------------------------------------------------------
__global__ void __launch_bounds__(256) agg_kernel(
    const float* __restrict__ ef,
    const float* __restrict__ radial,
    const int*   __restrict__ snd_,
    const float* __restrict__ Wr1,   // (8,8)
    const float* __restrict__ Wr2,   // (8,128)
    int N)
{
    int warp = (blockIdx.x * blockDim.x + threadIdx.x) >> 5;
    int lane = threadIdx.x & 31;
    if (warp >= N) return;
    int n = warp;

    int beg = g_off[n], end = g_off[n + 1];

    const float inv_sqrt8 = 0.35355339059327373f;
    const float inv_sqrt3 = 0.5773502691896258f;

    int grp  = lane >> 3;
    int srcA = (grp == 0) ? lane : ((grp == 1) ? lane + 16 : lane - 8);
    int srcB = (grp < 2)  ? lane + 8 : srcA;
    int cidx = (lane & 7) * 4;
    int jj   = lane & 7;

    float aA0 = 0.f, aA1 = 0.f, aA2 = 0.f, aA3 = 0.f;
    float aB0 = 0.f, aB1 = 0.f, aB2 = 0.f, aB3 = 0.f;

    for (int base = beg; base < end; base += 32) {
        int eid = 0, sndl = 0;
        if (base + lane < end) {
            eid  = __ldg(g_sorted + base + lane);
            sndl = __ldg(snd_ + eid);
        }
        int m = end - base; if (m > 32) m = 32;

        for (int j = 0; j < m; ++j) {
            int e   = __shfl_sync(0xffffffffu, eid,  j);
            int snd = __shfl_sync(0xffffffffu, sndl, j);

            // radial MLP hidden layer (lane computes h[lane&7])
            float h = 0.f;
            const float* r = radial + (size_t)e * 8;
            #pragma unroll
            for (int i = 0; i < 8; ++i)
                h = fmaf(__ldg(r + i), __ldg(Wr1 + i * 8 + jj), h);
            h = silu_f(h * inv_sqrt8);

            // producer w: Wr2 columns 4*lane..+3
            float w0 = 0.f, w1 = 0.f, w2 = 0.f, w3 = 0.f;
            #pragma unroll
            for (int q = 0; q < 8; ++q) {
                float hq = __shfl_sync(0xffffffffu, h, q);
                float4 wr = __ldg((const float4*)(Wr2 + q * 128 + lane * 4));
                w0 = fmaf(hq, wr.x, w0);
                w1 = fmaf(hq, wr.y, w1);
                w2 = fmaf(hq, wr.z, w2);
                w3 = fmaf(hq, wr.w, w3);
            }
            w0 *= inv_sqrt8; w1 *= inv_sqrt8; w2 *= inv_sqrt8; w3 *= inv_sqrt8;

            float wA0 = __shfl_sync(0xffffffffu, w0, srcA);
            float wA1 = __shfl_sync(0xffffffffu, w1, srcA);
            float wA2 = __shfl_sync(0xffffffffu, w2, srcA);
            float wA3 = __shfl_sync(0xffffffffu, w3, srcA);
            float wB0 = __shfl_sync(0xffffffffu, w0, srcB);
            float wB1 = __shfl_sync(0xffffffffu, w1, srcB);
            float wB2 = __shfl_sync(0xffffffffu, w2, srcB);
            float wB3 = __shfl_sync(0xffffffffu, w3, srcB);

            float4 sh = __ldg((const float4*)(ef + (size_t)e * 4));

            float vA0, vA1, vA2, vA3, vB0, vB1, vB2, vB3;

            if ((grp & 1) == 0) {
                float4 se = __ldg((const float4*)(g_sup + (size_t)snd * 32 + cidx));
                if (grp == 0) {
                    vA0 = wA0 * se.x * sh.x; vA1 = wA1 * se.y * sh.x;
                    vA2 = wA2 * se.z * sh.x; vA3 = wA3 * se.w * sh.x;
                    vB0 = wB0 * se.x * sh.z; vB1 = wB1 * se.y * sh.z;
                    vB2 = wB2 * se.z * sh.z; vB3 = wB3 * se.w * sh.z;
                } else {
                    vA0 = wA0 * se.x * sh.y; vA1 = wA1 * se.y * sh.y;
                    vA2 = wA2 * se.z * sh.y; vA3 = wA3 * se.w * sh.y;
                    vB0 = wA0 * se.x * sh.w; vB1 = wA1 * se.y * sh.w;
                    vB2 = wA2 * se.z * sh.w; vB3 = wA3 * se.w * sh.w;
                }
            } else {
                const float* vb = g_vup + (size_t)snd * 96 + cidx;
                if (grp == 1) {
                    float4 ve0 = __ldg((const float4*)(vb));
                    float4 ve1 = __ldg((const float4*)(vb + 32));
                    float4 ve2 = __ldg((const float4*)(vb + 64));
                    float d0 = ve0.x * sh.y + ve1.x * sh.z + ve2.x * sh.w;
                    float d1 = ve0.y * sh.y + ve1.y * sh.z + ve2.y * sh.w;
                    float d2 = ve0.z * sh.y + ve1.z * sh.z + ve2.z * sh.w;
                    float d3 = ve0.w * sh.y + ve1.w * sh.z + ve2.w * sh.w;
                    vA0 = wA0 * d0 * inv_sqrt3; vA1 = wA1 * d1 * inv_sqrt3;
                    vA2 = wA2 * d2 * inv_sqrt3; vA3 = wA3 * d3 * inv_sqrt3;
                    vB0 = wB0 * ve1.x * sh.x; vB1 = wB1 * ve1.y * sh.x;
                    vB2 = wB2 * ve1.z * sh.x; vB3 = wB3 * ve1.w * sh.x;
                } else {
                    float4 ve0 = __ldg((const float4*)(vb));
                    float4 ve2 = __ldg((const float4*)(vb + 64));
                    vA0 = wA0 * ve0.x * sh.x; vA1 = wA1 * ve0.y * sh.x;
                    vA2 = wA2 * ve0.z * sh.x; vA3 = wA3 * ve0.w * sh.x;
                    vB0 = wA0 * ve2.x * sh.x; vB1 = wA1 * ve2.y * sh.x;
                    vB2 = wA2 * ve2.z * sh.x; vB3 = wA3 * ve2.w * sh.x;
                }
            }

            aA0 += vA0; aA1 += vA1; aA2 += vA2; aA3 += vA3;
            aB0 += vB0; aB1 += vB1; aB2 += vB2; aB3 += vB3;
        }
    }

    const float qdeg = 0.25f; // 1/sqrt(16)
    float* dst = g_agg + (size_t)n * 256 + (lane >> 4) * 64 + (lane & 15) * 4;
    *(float4*)dst         = make_float4(aA0 * qdeg, aA1 * qdeg, aA2 * qdeg, aA3 * qdeg);
    *(float4*)(dst + 128) = make_float4(aB0 * qdeg, aB1 * qdeg, aB2 * qdeg, aB3 * qdeg);
}

// ---------------------------------------------------------------------------
// Kernel C: per-node down-projection + skip average + gated output.
// ---------------------------------------------------------------------------
__global__ void node_down_kernel(const float* __restrict__ Wds,  // (64,64)
                                 const float* __restrict__ Wdv,  // (64,32)
                                 float* __restrict__ out,
                                 int N)
{
    int warp = (blockIdx.x * blockDim.x + threadIdx.x) >> 5;
    int lane = threadIdx.x & 31;
    if (warp >= N) return;
    int n = warp;

    const float* ag = g_agg + (size_t)n * 256;
    float a0l  = ag[lane],        a0h  = ag[32 + lane];
    float a1l0 = ag[64 + lane],   a1h0 = ag[96 + lane];
    float a1l1 = ag[128 + lane],  a1h1 = ag[160 + lane];
    float a1l2 = ag[192 + lane],  a1h2 = ag[224 + lane];

    float sc0 = 0.f, sc1 = 0.f, vc0 = 0.f, vc1 = 0.f, vc2 = 0.f;

    #pragma unroll
    for (int c = 0; c < 32; ++c) {
        float b0 = __shfl_sync(0xffffffffu, a0l, c);
        float b1 = __shfl_sync(0xffffffffu, a0h, c);
        sc0 = fmaf(b0, __ldg(Wds + c * 64 + lane), sc0);
        sc0 = fmaf(b1, __ldg(Wds + (32 + c) * 64 + lane), sc0);
        sc1 = fmaf(b0, __ldg(Wds + c * 64 + 32 + lane), sc1);
        sc1 = fmaf(b1, __ldg(Wds + (32 + c) * 64 + 32 + lane), sc1);
        float wv0 = __ldg(Wdv + c * 32 + lane);
        float wv1 = __ldg(Wdv + (32 + c) * 32 + lane);
        vc0 = fmaf(__shfl_sync(0xffffffffu, a1l0, c), wv0, vc0);
        vc0 = fmaf(__shfl_sync(0xffffffffu, a1h0, c), wv1, vc0);
        vc1 = fmaf(__shfl_sync(0xffffffffu, a1l1, c), wv0, vc1);
        vc1 = fmaf(__shfl_sync(0xffffffffu, a1h1, c), wv1, vc1);
        vc2 = fmaf(__shfl_sync(0xffffffffu, a1l2, c), wv0, vc2);
        vc2 = fmaf(__shfl_sync(0xffffffffu, a1h2, c), wv1, vc2);
    }

    const float i2c = 0.125f; // 1/sqrt(64)
    float scl = 0.5f * (sc0 * i2c + g_skip_s[n * 64 + lane]);
    float sch = 0.5f * (sc1 * i2c + g_skip_s[n * 64 + 32 + lane]);
    float feat = silu_f(scl);
    float gate = silu_f(sch);

    float vg0 = 0.5f * (vc0 * i2c + g_skip_v[n * 96 +      lane]) * gate;
    float vg1 = 0.5f * (vc1 * i2c + g_skip_v[n * 96 + 32 + lane]) * gate;
    float vg2 = 0.5f * (vc2 * i2c + g_skip_v[n * 96 + 64 + lane]) * gate;

    float* o = out + (size_t)n * 128;
    o[lane] = feat;
    o[32 + 3 * lane + 0] = vg0;
    o[32 + 3 * lane + 1] = vg1;
    o[32 + 3 * lane + 2] = vg2;
}

// ---------------------------------------------------------------------------
extern "C" void kernel_launch(void* const* d_in, const int* in_sizes, int n_in,
                              void* d_out, int out_size)
{
    const float* nf      = (const float*)d_in[0];
    const float* ef      = (const float*)d_in[1];
    const float* radial  = (const float*)d_in[2];
    const int*   snd     = (const int*)  d_in[3];
    const int*   rcv     = (const int*)  d_in[4];
    const int*   species = (const int*)  d_in[5];
    const float* Wus     = (const float*)d_in[6];
    const float* Wuv     = (const float*)d_in[7];
    const float* Wr1     = (const float*)d_in[8];
    const float* Wr2     = (const float*)d_in[9];
    const float* Wds     = (const float*)d_in[10];
    const float* Wdv     = (const float*)d_in[11];
    const float* Wss     = (const float*)d_in[12];
    const float* Wsv     = (const float*)d_in[13];
    float* out = (float*)d_out;

    int N = in_sizes[0] / 128;
    int E = in_sizes[3];
    int nb = (N + 1023) / 1024;

    // node_up also zeroes g_cnt (must precede hist)
    node_up_kernel  <<<(N + 7) / 8, 256>>>(nf, species, Wus, Wuv, Wss, Wsv, N);
    hist_kernel     <<<(E + 255) / 256, 256>>>(rcv, E);
    scan1_kernel    <<<nb, 1024>>>(N);
    scan2_kernel    <<<1, 32>>>(nb, N);
    scan3_kernel    <<<nb, 1024>>>(N);
    reorder_kernel  <<<(E + 255) / 256, 256>>>(rcv, E);
    agg_kernel      <<<(N + 7) / 8, 256>>>(ef, radial, snd, Wr1, Wr2, N);
    node_down_kernel<<<(N + 7) / 8, 256>>>(Wds, Wdv, out, N);
}